// round 2
// baseline (speedup 1.0000x reference)
#include <cuda_runtime.h>
#include <math.h>

#define TT 256
#define DD 2048
#define NH 16
#define HDIM 128
#define NE 64
#define TOPK 8
#define DFF 1024
#define EPSF 1e-5f
#define ASCALE 0.08838834764831845f
#define NEGINF -3.4028234663852886e38f

// ---------------- scratch (device globals: alloc-free) ----------------
__device__ float g_xn[TT*DD];
__device__ float g_qb[TT*DD];
__device__ float g_kb[TT*DD];
__device__ float g_vb[TT*DD];
__device__ float g_sc[NH*TT*TT];
__device__ float g_ctx[TT*DD];
__device__ float g_x2[TT*DD];
__device__ float g_x3[TT*DD];
__device__ float g_act[(size_t)NE*256*DFF];
__device__ int   g_cnt[NE];
__device__ int   g_tok[NE*256];
__device__ float g_wgt[NE*256];

// ---------------- RMSNorm: one block per row ----------------
__global__ void rms_kernel(const float* __restrict__ in, const float* __restrict__ w,
                           float* __restrict__ out)
{
    int row = blockIdx.x;
    const float* xr = in + (size_t)row * DD;
    float ss = 0.f;
    for (int i = threadIdx.x; i < DD; i += 256) { float v = xr[i]; ss += v * v; }
    __shared__ float red[256];
    red[threadIdx.x] = ss; __syncthreads();
    for (int s = 128; s > 0; s >>= 1) {
        if (threadIdx.x < s) red[threadIdx.x] += red[threadIdx.x + s];
        __syncthreads();
    }
    float r = rsqrtf(red[0] / (float)DD + EPSF);
    for (int i = threadIdx.x; i < DD; i += 256)
        out[(size_t)row * DD + i] = xr[i] * r * w[i];
}

// ---------------- RoPE in place on q,k ([T, H*HD] layout) ----------------
__global__ void rope_kernel(float* __restrict__ q, float* __restrict__ k)
{
    int t = blockIdx.x / NH, h = blockIdx.x % NH;
    int i = threadIdx.x; // 64
    float inv = __expf(-((float)i / 64.0f) * 9.210340371976184f); // 10000^(-i/64)
    float ang = (float)t * inv;
    float c = cosf(ang), s = sinf(ang);
    int base = t * DD + h * HDIM;
    float q1 = q[base + i], q2 = q[base + 64 + i];
    q[base + i]      = q1 * c - q2 * s;
    q[base + 64 + i] = q1 * s + q2 * c;
    float k1 = k[base + i], k2 = k[base + 64 + i];
    k[base + i]      = k1 * c - k2 * s;
    k[base + 64 + i] = k1 * s + k2 * c;
}

// ---------------- GEMM C[M,N] = alpha * A[M,K] @ B[N,K]^T (+res) , batched z ----------------
// BM=BN=64, BK=16, 256 threads, 4x4 per thread. M,N multiples of 64, K multiple of 16.
__global__ void gemm_nt(const float* __restrict__ A, int lda, long long sA,
                        const float* __restrict__ B, int ldb, long long sB,
                        float* __restrict__ C, int ldc, long long sC,
                        int K, const float* __restrict__ res,
                        float alpha, int causal)
{
    long long z = blockIdx.z;
    A += z * sA; B += z * sB; C += z * sC;
    __shared__ float As[16][64];
    __shared__ float Bs[16][64];
    int bm = blockIdx.y * 64, bn = blockIdx.x * 64;
    int tid = threadIdx.x;
    int lr = tid >> 2, lc = tid & 3;
    int ty = tid >> 4, tx = tid & 15;
    float acc[4][4];
#pragma unroll
    for (int i = 0; i < 4; i++)
#pragma unroll
        for (int j = 0; j < 4; j++) acc[i][j] = 0.f;

    for (int k0 = 0; k0 < K; k0 += 16) {
        float4 a4 = *(const float4*)(A + (size_t)(bm + lr) * lda + k0 + lc * 4);
        float4 b4 = *(const float4*)(B + (size_t)(bn + lr) * ldb + k0 + lc * 4);
        As[lc*4+0][lr] = a4.x; As[lc*4+1][lr] = a4.y; As[lc*4+2][lr] = a4.z; As[lc*4+3][lr] = a4.w;
        Bs[lc*4+0][lr] = b4.x; Bs[lc*4+1][lr] = b4.y; Bs[lc*4+2][lr] = b4.z; Bs[lc*4+3][lr] = b4.w;
        __syncthreads();
#pragma unroll
        for (int kk = 0; kk < 16; kk++) {
            float4 av = *(const float4*)&As[kk][ty*4];
            float4 bv = *(const float4*)&Bs[kk][tx*4];
            float ar[4] = {av.x, av.y, av.z, av.w};
            float br[4] = {bv.x, bv.y, bv.z, bv.w};
#pragma unroll
            for (int i = 0; i < 4; i++)
#pragma unroll
                for (int j = 0; j < 4; j++) acc[i][j] += ar[i] * br[j];
        }
        __syncthreads();
    }
#pragma unroll
    for (int i = 0; i < 4; i++) {
        int row = bm + ty*4 + i;
#pragma unroll
        for (int j = 0; j < 4; j++) {
            int col = bn + tx*4 + j;
            float v = acc[i][j] * alpha;
            if (causal && col > row) v = NEGINF;
            if (res) v += res[(size_t)row * ldc + col];
            C[(size_t)row * ldc + col] = v;
        }
    }
}

// ---------------- GEMM C[M,N] = A[M,K] @ B[K,N], batched z (for P@V) ----------------
__global__ void gemm_nn(const float* __restrict__ A, int lda, long long sA,
                        const float* __restrict__ B, int ldb, long long sB,
                        float* __restrict__ C, int ldc, long long sC,
                        int K)
{
    long long z = blockIdx.z;
    A += z * sA; B += z * sB; C += z * sC;
    __shared__ float As[16][64];
    __shared__ float Bs[16][64];
    int bm = blockIdx.y * 64, bn = blockIdx.x * 64;
    int tid = threadIdx.x;
    int lr = tid >> 2, lc = tid & 3;
    int ty = tid >> 4, tx = tid & 15;
    float acc[4][4];
#pragma unroll
    for (int i = 0; i < 4; i++)
#pragma unroll
        for (int j = 0; j < 4; j++) acc[i][j] = 0.f;

    for (int k0 = 0; k0 < K; k0 += 16) {
        float4 a4 = *(const float4*)(A + (size_t)(bm + lr) * lda + k0 + lc * 4);
        As[lc*4+0][lr] = a4.x; As[lc*4+1][lr] = a4.y; As[lc*4+2][lr] = a4.z; As[lc*4+3][lr] = a4.w;
#pragma unroll
        for (int i = 0; i < 4; i++) {
            int kr = i * 4 + (tid >> 6);
            Bs[kr][tid & 63] = B[(size_t)(k0 + kr) * ldb + bn + (tid & 63)];
        }
        __syncthreads();
#pragma unroll
        for (int kk = 0; kk < 16; kk++) {
            float4 av = *(const float4*)&As[kk][ty*4];
            float4 bv = *(const float4*)&Bs[kk][tx*4];
            float ar[4] = {av.x, av.y, av.z, av.w};
            float br[4] = {bv.x, bv.y, bv.z, bv.w};
#pragma unroll
            for (int i = 0; i < 4; i++)
#pragma unroll
                for (int j = 0; j < 4; j++) acc[i][j] += ar[i] * br[j];
        }
        __syncthreads();
    }
#pragma unroll
    for (int i = 0; i < 4; i++) {
        int row = bm + ty*4 + i;
#pragma unroll
        for (int j = 0; j < 4; j++)
            C[(size_t)row * ldc + bn + tx*4 + j] = acc[i][j];
    }
}

// ---------------- softmax over rows of 256 (in place) ----------------
__global__ void softmax_kernel(float* __restrict__ s)
{
    int row = blockIdx.x;
    float* p = s + (size_t)row * TT;
    int i = threadIdx.x;
    float v = p[i];
    __shared__ float red[256];
    red[i] = v; __syncthreads();
    for (int st = 128; st > 0; st >>= 1) {
        if (i < st) red[i] = fmaxf(red[i], red[i + st]);
        __syncthreads();
    }
    float m = red[0]; __syncthreads();
    float e = expf(v - m);
    red[i] = e; __syncthreads();
    for (int st = 128; st > 0; st >>= 1) {
        if (i < st) red[i] += red[i + st];
        __syncthreads();
    }
    p[i] = e / red[0];
}

// ---------------- copy (out = x2 base for residual atomics) ----------------
__global__ void copy_kernel(const float* __restrict__ a, float* __restrict__ b, int n)
{
    int i = blockIdx.x * 256 + threadIdx.x;
    if (i < n) b[i] = a[i];
}

__global__ void zero_cnt_kernel(int* cnt)
{
    if (threadIdx.x < NE) cnt[threadIdx.x] = 0;
}

// ---------------- router: logits, softmax, top-8, scatter to expert lists ----------------
__global__ void router_kernel(const float* __restrict__ x3, const float* __restrict__ gw,
                              int* __restrict__ cnt, int* __restrict__ tok, float* __restrict__ wgt)
{
    int t = blockIdx.x;
    __shared__ float xr[DD];
    __shared__ float lg[NE];
    for (int i = threadIdx.x; i < DD; i += blockDim.x) xr[i] = x3[(size_t)t * DD + i];
    __syncthreads();
    if (threadIdx.x < NE) {
        const float* wrow = gw + (size_t)threadIdx.x * DD;
        float acc = 0.f;
        for (int j = 0; j < DD; j++) acc += xr[j] * wrow[j];
        lg[threadIdx.x] = acc;
    }
    __syncthreads();
    if (threadIdx.x == 0) {
        float mx = -1e30f;
        for (int e = 0; e < NE; e++) mx = fmaxf(mx, lg[e]);
        float sum = 0.f;
        for (int e = 0; e < NE; e++) { lg[e] = expf(lg[e] - mx); sum += lg[e]; }
        bool used[NE];
        for (int e = 0; e < NE; e++) used[e] = false;
        for (int s = 0; s < TOPK; s++) {
            int bi = 0; float bv = -1.f;
            for (int e = 0; e < NE; e++)
                if (!used[e] && lg[e] > bv) { bv = lg[e]; bi = e; }
            used[bi] = true;
            int pos = atomicAdd(&cnt[bi], 1);
            tok[bi * 256 + pos] = t;
            wgt[bi * 256 + pos] = bv / sum;
        }
    }
}

// ---------------- grouped MoE gate_up: act = silu(x3@Wg^T) * (x3@Wu^T) * w ----------------
// BM=32, BN=64 (within DFF), BK=16; 256 threads, each 2x4 per matrix.
__global__ void moe_gate_up(const float* __restrict__ x3, const float* __restrict__ w_gu,
                            const int* __restrict__ cnt, const int* __restrict__ tok,
                            const float* __restrict__ wgt, float* __restrict__ act)
{
    int e = blockIdx.z;
    int nt = cnt[e];
    int m0 = blockIdx.y * 32;
    if (m0 >= nt) return;
    int n0 = blockIdx.x * 64;
    __shared__ int   stok[32];
    __shared__ float As[16][32];
    __shared__ float Bg[16][64];
    __shared__ float Bu[16][64];
    int tid = threadIdx.x;
    if (tid < 32) stok[tid] = (m0 + tid < nt) ? tok[e * 256 + m0 + tid] : -1;
    __syncthreads();
    int ty = tid >> 4, tx = tid & 15;
    float ag[2][4], au[2][4];
#pragma unroll
    for (int i = 0; i < 2; i++)
#pragma unroll
        for (int j = 0; j < 4; j++) { ag[i][j] = 0.f; au[i][j] = 0.f; }
    const float* Wg = w_gu + (size_t)e * (2 * DFF) * DD;

    for (int k0 = 0; k0 < DD; k0 += 16) {
        {
            int r = tid >> 3, c2 = tid & 7;
            int tk = stok[r];
            float2 v = (tk >= 0) ? *(const float2*)(x3 + (size_t)tk * DD + k0 + c2 * 2)
                                 : make_float2(0.f, 0.f);
            As[c2*2][r] = v.x; As[c2*2+1][r] = v.y;
        }
        {
            int r = tid >> 2, c4 = tid & 3;
            float4 gv = *(const float4*)(Wg + (size_t)(n0 + r) * DD + k0 + c4 * 4);
            float4 uv = *(const float4*)(Wg + (size_t)(DFF + n0 + r) * DD + k0 + c4 * 4);
            Bg[c4*4+0][r] = gv.x; Bg[c4*4+1][r] = gv.y; Bg[c4*4+2][r] = gv.z; Bg[c4*4+3][r] = gv.w;
            Bu[c4*4+0][r] = uv.x; Bu[c4*4+1][r] = uv.y; Bu[c4*4+2][r] = uv.z; Bu[c4*4+3][r] = uv.w;
        }
        __syncthreads();
#pragma unroll
        for (int kk = 0; kk < 16; kk++) {
            float a0 = As[kk][ty*2], a1 = As[kk][ty*2+1];
            float4 bg = *(const float4*)&Bg[kk][tx*4];
            float4 bu = *(const float4*)&Bu[kk][tx*4];
            float bgr[4] = {bg.x, bg.y, bg.z, bg.w};
            float bur[4] = {bu.x, bu.y, bu.z, bu.w};
#pragma unroll
            for (int j = 0; j < 4; j++) {
                ag[0][j] += a0 * bgr[j]; ag[1][j] += a1 * bgr[j];
                au[0][j] += a0 * bur[j]; au[1][j] += a1 * bur[j];
            }
        }
        __syncthreads();
    }
#pragma unroll
    for (int i = 0; i < 2; i++) {
        int r = ty*2 + i;
        if (m0 + r < nt) {
            float w = wgt[e * 256 + m0 + r];
#pragma unroll
            for (int j = 0; j < 4; j++) {
                float g = ag[i][j];
                float sg = g / (1.f + expf(-g));
                act[((size_t)(e * 256 + m0 + r)) * DFF + n0 + tx*4 + j] = sg * au[i][j] * w;
            }
        }
    }
}

// ---------------- grouped MoE down: out[t, :] += act_row @ down_w[e]^T ----------------
__global__ void moe_down(const float* __restrict__ act, const float* __restrict__ w_down,
                         const int* __restrict__ cnt, const int* __restrict__ tok,
                         float* __restrict__ out)
{
    int e = blockIdx.z;
    int nt = cnt[e];
    int m0 = blockIdx.y * 32;
    if (m0 >= nt) return;
    int n0 = blockIdx.x * 64;
    __shared__ float As[16][32];
    __shared__ float Bs[16][64];
    int tid = threadIdx.x;
    int ty = tid >> 4, tx = tid & 15;
    float acc[2][4];
#pragma unroll
    for (int i = 0; i < 2; i++)
#pragma unroll
        for (int j = 0; j < 4; j++) acc[i][j] = 0.f;
    const float* W = w_down + (size_t)e * DD * DFF;

    for (int k0 = 0; k0 < DFF; k0 += 16) {
        {
            int r = tid >> 3, c2 = tid & 7;
            float2 v = (m0 + r < nt)
                ? *(const float2*)(act + ((size_t)(e * 256 + m0 + r)) * DFF + k0 + c2 * 2)
                : make_float2(0.f, 0.f);
            As[c2*2][r] = v.x; As[c2*2+1][r] = v.y;
        }
        {
            int r = tid >> 2, c4 = tid & 3;
            float4 bv = *(const float4*)(W + (size_t)(n0 + r) * DFF + k0 + c4 * 4);
            Bs[c4*4+0][r] = bv.x; Bs[c4*4+1][r] = bv.y; Bs[c4*4+2][r] = bv.z; Bs[c4*4+3][r] = bv.w;
        }
        __syncthreads();
#pragma unroll
        for (int kk = 0; kk < 16; kk++) {
            float a0 = As[kk][ty*2], a1 = As[kk][ty*2+1];
            float4 bv = *(const float4*)&Bs[kk][tx*4];
            float br[4] = {bv.x, bv.y, bv.z, bv.w};
#pragma unroll
            for (int j = 0; j < 4; j++) {
                acc[0][j] += a0 * br[j];
                acc[1][j] += a1 * br[j];
            }
        }
        __syncthreads();
    }
#pragma unroll
    for (int i = 0; i < 2; i++) {
        int r = ty*2 + i;
        if (m0 + r < nt) {
            int t = tok[e * 256 + m0 + r];
#pragma unroll
            for (int j = 0; j < 4; j++)
                atomicAdd(&out[(size_t)t * DD + n0 + tx*4 + j], acc[i][j]);
        }
    }
}

// ---------------- host launch ----------------
extern "C" void kernel_launch(void* const* d_in, const int* in_sizes, int n_in,
                              void* d_out, int out_size)
{
    const float* x    = (const float*)d_in[0];
    const float* ln1  = (const float*)d_in[1];
    const float* qw   = (const float*)d_in[2];
    const float* kw   = (const float*)d_in[3];
    const float* vw   = (const float*)d_in[4];
    const float* qn   = (const float*)d_in[5];
    const float* kn   = (const float*)d_in[6];
    const float* ow   = (const float*)d_in[7];
    const float* ln2  = (const float*)d_in[8];
    const float* gw   = (const float*)d_in[9];
    const float* guw  = (const float*)d_in[10];
    const float* dw   = (const float*)d_in[11];
    float* out = (float*)d_out;

    float *p_xn, *p_qb, *p_kb, *p_vb, *p_sc, *p_ctx, *p_x2, *p_x3, *p_act, *p_wgt;
    int *p_cnt, *p_tok;
    cudaGetSymbolAddress((void**)&p_xn,  g_xn);
    cudaGetSymbolAddress((void**)&p_qb,  g_qb);
    cudaGetSymbolAddress((void**)&p_kb,  g_kb);
    cudaGetSymbolAddress((void**)&p_vb,  g_vb);
    cudaGetSymbolAddress((void**)&p_sc,  g_sc);
    cudaGetSymbolAddress((void**)&p_ctx, g_ctx);
    cudaGetSymbolAddress((void**)&p_x2,  g_x2);
    cudaGetSymbolAddress((void**)&p_x3,  g_x3);
    cudaGetSymbolAddress((void**)&p_act, g_act);
    cudaGetSymbolAddress((void**)&p_cnt, g_cnt);
    cudaGetSymbolAddress((void**)&p_tok, g_tok);
    cudaGetSymbolAddress((void**)&p_wgt, g_wgt);

    // 1. xn = rms(x, ln1)
    rms_kernel<<<TT, 256>>>(x, ln1, p_xn);

    // 2. q/k/v linear: [256,2048] = xn @ W^T
    dim3 gqkv(DD/64, TT/64, 1);
    gemm_nt<<<gqkv, 256>>>(p_xn, DD, 0, qw, DD, 0, p_qb, DD, 0, DD, nullptr, 1.f, 0);
    gemm_nt<<<gqkv, 256>>>(p_xn, DD, 0, kw, DD, 0, p_kb, DD, 0, DD, nullptr, 1.f, 0);
    gemm_nt<<<gqkv, 256>>>(p_xn, DD, 0, vw, DD, 0, p_vb, DD, 0, DD, nullptr, 1.f, 0);

    // 3. q/k RMS over full D (in place)
    rms_kernel<<<TT, 256>>>(p_qb, qn, p_qb);
    rms_kernel<<<TT, 256>>>(p_kb, kn, p_kb);

    // 4. RoPE in place
    rope_kernel<<<TT * NH, 64>>>(p_qb, p_kb);

    // 5. scores per head: S[h,q,k] = SCALE * q·k, causal mask
    dim3 gsc(TT/64, TT/64, NH);
    gemm_nt<<<gsc, 256>>>(p_qb, DD, HDIM, p_kb, DD, HDIM,
                          p_sc, TT, (long long)TT*TT, HDIM, nullptr, ASCALE, 1);

    // 6. softmax rows
    softmax_kernel<<<NH * TT, 256>>>(p_sc);

    // 7. ctx = P @ V per head, write into [t, h*128+d] layout
    dim3 gpv(HDIM/64, TT/64, NH);
    gemm_nn<<<gpv, 256>>>(p_sc, TT, (long long)TT*TT, p_vb, DD, HDIM,
                          p_ctx, DD, HDIM, TT);

    // 8. x2 = x + ctx @ o_w^T
    gemm_nt<<<gqkv, 256>>>(p_ctx, DD, 0, ow, DD, 0, p_x2, DD, 0, DD, x, 1.f, 0);

    // 9. out = x2 (residual base for MoE atomics)
    copy_kernel<<<(TT*DD + 255)/256, 256>>>(p_x2, out, TT*DD);

    // 10. x3 = rms(x2, ln2)
    rms_kernel<<<TT, 256>>>(p_x2, ln2, p_x3);

    // 11-12. router -> expert token lists
    zero_cnt_kernel<<<1, 64>>>(p_cnt);
    router_kernel<<<TT, 256>>>(p_x3, gw, p_cnt, p_tok, p_wgt);

    // 13. grouped gate_up + silu*up*weight
    dim3 ggu(DFF/64, 8, NE);
    moe_gate_up<<<ggu, 256>>>(p_x3, guw, p_cnt, p_tok, p_wgt, p_act);

    // 14. grouped down-proj, atomic accumulate into out
    dim3 gdn(DD/64, 8, NE);
    moe_down<<<gdn, 256>>>(p_act, dw, p_cnt, p_tok, out);
}